// round 15
// baseline (speedup 1.0000x reference)
#include <cuda_runtime.h>
#include <cuda_bf16.h>
#include <cuda_fp16.h>
#include <cstdint>

#define NN  100000
#define EE  1600000
#define FIN 512
#define C1  128    // 2*H
#define HH  64

// ---------------- scratch (no allocations allowed) ----------------
__device__ __align__(16) __half g_t1h[(size_t)NN * C1];  // x @ W1 (fp16)
__device__ __align__(16) __half g_hh[(size_t)NN * C1];   // relu(agg(t1)+b1) (fp16)
__device__ __align__(16) __half g_ph[(size_t)NN * C1];   // h @ [Wmu|Wls] (fp16)
__device__ float g_dinv[NN];
__device__ int   g_deg[NN];
__device__ int   g_rowptr[NN + 1];
__device__ int   g_cursor[NN];
__device__ __align__(8) int2 g_edge[EE];   // {src, __float_as_int(dinv[src])}
__device__ int   g_partial[128];
// weights as tf32 bit patterns, TRANSPOSED: [n][k]
__device__ __align__(16) uint32_t g_w1t[C1 * FIN];   // [128][512]
__device__ __align__(16) uint32_t g_wct[C1 * C1];    // [128][128]

// ---------------- helpers ----------------
__device__ __forceinline__ uint32_t smem_u32(const void* p) {
    uint32_t a;
    asm("{ .reg .u64 t; cvta.to.shared.u64 t, %1; cvt.u32.u64 %0, t; }" : "=r"(a) : "l"(p));
    return a;
}
__device__ __forceinline__ uint32_t f2tf(float f) {
    uint32_t u;
    asm("cvt.rna.tf32.f32 %0, %1;" : "=r"(u) : "f"(f));
    return u;
}
__device__ __forceinline__ void ldsm_x4(uint32_t& r0, uint32_t& r1, uint32_t& r2, uint32_t& r3,
                                        uint32_t addr) {
    asm volatile("ldmatrix.sync.aligned.m8n8.x4.shared.b16 {%0,%1,%2,%3}, [%4];"
                 : "=r"(r0), "=r"(r1), "=r"(r2), "=r"(r3) : "r"(addr));
}
__device__ __forceinline__ void mma_tf32(float* c, const uint32_t* a, const uint32_t* b) {
    asm volatile(
        "mma.sync.aligned.m16n8k8.row.col.f32.tf32.tf32.f32 "
        "{%0,%1,%2,%3}, {%4,%5,%6,%7}, {%8,%9}, {%0,%1,%2,%3};"
        : "+f"(c[0]), "+f"(c[1]), "+f"(c[2]), "+f"(c[3])
        : "r"(a[0]), "r"(a[1]), "r"(a[2]), "r"(a[3]), "r"(b[0]), "r"(b[1]));
}

// ---------------- weight preprocessing + deg init (fused) ------------------
__global__ void k_prep_w(const float* __restrict__ W1,
                         const float* __restrict__ Wmu, const float* __restrict__ Wls) {
    int idx = blockIdx.x * 256 + threadIdx.x;
    if (idx < C1 * FIN) {
        int n = idx >> 9, k = idx & 511;
        g_w1t[idx] = f2tf(W1[k * C1 + n]);
    } else if (idx < C1 * FIN + C1 * C1) {
        int j = idx - C1 * FIN;
        int n = j >> 7, k = j & 127;
        float w = (n < HH) ? Wmu[k * HH + n] : Wls[k * HH + (n - HH)];
        g_wct[j] = f2tf(w);
    }
    if (idx < NN) g_deg[idx] = 1;   // self-loop init (fused deg_init)
}

// ---------------- graph preprocessing ----------------
__global__ void k_deg_count(const int* __restrict__ ei) {
    int e = blockIdx.x * blockDim.x + threadIdx.x;
    if (e < EE) atomicAdd(&g_deg[ei[EE + e]], 1);
}

__global__ void k_scan_local() {
    __shared__ int sd[1024];
    int t = threadIdx.x;
    int i = blockIdx.x * 1024 + t;
    int v = (i < NN) ? (g_deg[i] - 1) : 0;
    sd[t] = v;
    __syncthreads();
#pragma unroll
    for (int off = 1; off < 1024; off <<= 1) {
        int x = (t >= off) ? sd[t - off] : 0;
        __syncthreads();
        sd[t] += x;
        __syncthreads();
    }
    if (i < NN) g_rowptr[i] = sd[t] - v;
    if (t == 1023) g_partial[blockIdx.x] = sd[1023];
}

__global__ void k_add_offsets() {
    __shared__ int base;
    int i = blockIdx.x * 256 + threadIdx.x;
    if (threadIdx.x == 0) {
        int nb = blockIdx.x >> 2;
        int s = 0;
        for (int b = 0; b < nb; b++) s += g_partial[b];
        base = s;
    }
    __syncthreads();
    if (i < NN) {
        int r = g_rowptr[i] + base;
        g_rowptr[i] = r;
        g_cursor[i] = r;
        g_dinv[i] = rsqrtf((float)g_deg[i]);
    }
    if (i == 0) g_rowptr[NN] = EE;
}

// scatter: pack {src, dinv[src]} so aggregation never gathers dinv randomly
__global__ void k_scatter(const int* __restrict__ ei) {
    int e = blockIdx.x * blockDim.x + threadIdx.x;
    if (e < EE) {
        int s = ei[e];
        int d = ei[EE + e];
        int p = atomicAdd(&g_cursor[d], 1);
        g_edge[p] = make_int2(s, __float_as_int(g_dinv[s]));
    }
}

// ---------------- GEMM1 (mma.sync tf32) — R10 shape, measured 107us --------
#define TF_STRIDE 144

__global__ void __launch_bounds__(256, 2)
k_gemm1(const float* __restrict__ x) {
    __shared__ __align__(16) unsigned char sA[128 * TF_STRIDE];
    __shared__ __align__(16) unsigned char sW[128 * TF_STRIDE];

    const int tid = threadIdx.x;
    const int wid = tid >> 5, lane = tid & 31;
    const int warp_m = wid & 3;
    const int warp_n = wid >> 2;
    const int block_row = blockIdx.x * 128;

    const uint32_t sA_u = smem_u32(sA), sW_u = smem_u32(sW);

    float c[2][8][4];
#pragma unroll
    for (int mi = 0; mi < 2; mi++)
#pragma unroll
        for (int ni = 0; ni < 8; ni++)
#pragma unroll
            for (int q = 0; q < 4; q++) c[mi][ni][q] = 0.f;

    const int arow = lane & 15;
    const int acolg = (lane >> 4) * 16;
    const int wrow = (lane >> 4) * 8 + (lane & 7);
    const int wkh  = ((lane >> 3) & 1) * 16;
    const int st_r = tid >> 3, st_c = tid & 7;

    for (int kc = 0; kc < FIN / 32; kc++) {
#pragma unroll
        for (int l = 0; l < 4; l++) {
            int r = st_r + l * 32;
            int grow = block_row + r;
            float4 v = make_float4(0.f, 0.f, 0.f, 0.f);
            if (grow < NN) v = *(const float4*)&x[(size_t)grow * FIN + kc * 32 + st_c * 4];
            uint4 t = make_uint4(f2tf(v.x), f2tf(v.y), f2tf(v.z), f2tf(v.w));
            *(uint4*)(sA + r * TF_STRIDE + st_c * 16) = t;
        }
#pragma unroll
        for (int l = 0; l < 4; l++) {
            int r = st_r + l * 32;
            *(uint4*)(sW + r * TF_STRIDE + st_c * 16) =
                *(const uint4*)&g_w1t[(size_t)r * FIN + kc * 32 + st_c * 4];
        }
        __syncthreads();

#pragma unroll
        for (int slab = 0; slab < 4; slab++) {
            uint32_t a[2][4];
#pragma unroll
            for (int mi = 0; mi < 2; mi++) {
                uint32_t aoff = (uint32_t)(warp_m * 32 + mi * 16 + arow) * TF_STRIDE
                              + slab * 32 + acolg;
                ldsm_x4(a[mi][0], a[mi][1], a[mi][2], a[mi][3], sA_u + aoff);
            }
            uint32_t b[8][2];
#pragma unroll
            for (int nt2 = 0; nt2 < 4; nt2++) {
                uint32_t boff = (uint32_t)(warp_n * 64 + nt2 * 16 + wrow) * TF_STRIDE
                              + slab * 32 + wkh;
                ldsm_x4(b[nt2 * 2][0], b[nt2 * 2][1], b[nt2 * 2 + 1][0], b[nt2 * 2 + 1][1],
                        sW_u + boff);
            }
#pragma unroll
            for (int mi = 0; mi < 2; mi++)
#pragma unroll
                for (int nt = 0; nt < 8; nt++)
                    mma_tf32(c[mi][nt], a[mi], b[nt]);
        }
        __syncthreads();
    }

    const int qrow = lane >> 2;
    const int qcol = (lane & 3) * 2;
#pragma unroll
    for (int mi = 0; mi < 2; mi++) {
        int r0 = block_row + warp_m * 32 + mi * 16 + qrow;
#pragma unroll
        for (int ni = 0; ni < 8; ni++) {
            int col = warp_n * 64 + ni * 8 + qcol;
            if (r0 < NN)
                *(__half2*)&g_t1h[(size_t)r0 * C1 + col] =
                    __floats2half2_rn(c[mi][ni][0], c[mi][ni][1]);
            if (r0 + 8 < NN)
                *(__half2*)&g_t1h[(size_t)(r0 + 8) * C1 + col] =
                    __floats2half2_rn(c[mi][ni][2], c[mi][ni][3]);
        }
    }
}

// ---------------- GEMM2b: p(fp16) = h(fp16) @ [Wmu|Wls], tf32, zero params -
__global__ void __launch_bounds__(256, 2)
k_gemm2b() {
    __shared__ __align__(16) unsigned char sA[128 * TF_STRIDE];
    __shared__ __align__(16) unsigned char sW[128 * TF_STRIDE];

    const int tid = threadIdx.x;
    const int wid = tid >> 5, lane = tid & 31;
    const int warp_m = wid & 3;
    const int warp_n = wid >> 2;
    const int block_row = blockIdx.x * 128;

    const uint32_t sA_u = smem_u32(sA), sW_u = smem_u32(sW);

    float c[2][8][4];
#pragma unroll
    for (int mi = 0; mi < 2; mi++)
#pragma unroll
        for (int ni = 0; ni < 8; ni++)
#pragma unroll
            for (int q = 0; q < 4; q++) c[mi][ni][q] = 0.f;

    const int arow = lane & 15;
    const int acolg = (lane >> 4) * 16;
    const int wrow = (lane >> 4) * 8 + (lane & 7);
    const int wkh  = ((lane >> 3) & 1) * 16;
    const int st_r = tid >> 3, st_c = tid & 7;

#pragma unroll 1
    for (int kc = 0; kc < C1 / 32; kc++) {
#pragma unroll
        for (int l = 0; l < 4; l++) {
            int r = st_r + l * 32;
            int grow = block_row + r;
            float2 f0 = make_float2(0.f, 0.f), f1 = make_float2(0.f, 0.f);
            if (grow < NN) {
                uint2 hv = *(const uint2*)&g_hh[(size_t)grow * C1 + kc * 32 + st_c * 4];
                f0 = __half22float2(*reinterpret_cast<__half2*>(&hv.x));
                f1 = __half22float2(*reinterpret_cast<__half2*>(&hv.y));
            }
            uint4 t = make_uint4(f2tf(f0.x), f2tf(f0.y), f2tf(f1.x), f2tf(f1.y));
            *(uint4*)(sA + r * TF_STRIDE + st_c * 16) = t;
        }
#pragma unroll
        for (int l = 0; l < 4; l++) {
            int r = st_r + l * 32;
            *(uint4*)(sW + r * TF_STRIDE + st_c * 16) =
                *(const uint4*)&g_wct[(size_t)r * C1 + kc * 32 + st_c * 4];
        }
        __syncthreads();

#pragma unroll
        for (int slab = 0; slab < 4; slab++) {
            uint32_t a[2][4];
#pragma unroll
            for (int mi = 0; mi < 2; mi++) {
                uint32_t aoff = (uint32_t)(warp_m * 32 + mi * 16 + arow) * TF_STRIDE
                              + slab * 32 + acolg;
                ldsm_x4(a[mi][0], a[mi][1], a[mi][2], a[mi][3], sA_u + aoff);
            }
            uint32_t b[8][2];
#pragma unroll
            for (int nt2 = 0; nt2 < 4; nt2++) {
                uint32_t boff = (uint32_t)(warp_n * 64 + nt2 * 16 + wrow) * TF_STRIDE
                              + slab * 32 + wkh;
                ldsm_x4(b[nt2 * 2][0], b[nt2 * 2][1], b[nt2 * 2 + 1][0], b[nt2 * 2 + 1][1],
                        sW_u + boff);
            }
#pragma unroll
            for (int mi = 0; mi < 2; mi++)
#pragma unroll
                for (int nt = 0; nt < 8; nt++)
                    mma_tf32(c[mi][nt], a[mi], b[nt]);
        }
        __syncthreads();
    }

    const int qrow = lane >> 2;
    const int qcol = (lane & 3) * 2;
#pragma unroll
    for (int mi = 0; mi < 2; mi++) {
        int r0 = block_row + warp_m * 32 + mi * 16 + qrow;
#pragma unroll
        for (int ni = 0; ni < 8; ni++) {
            int col = warp_n * 64 + ni * 8 + qcol;
            if (r0 < NN)
                *(__half2*)&g_ph[(size_t)r0 * C1 + col] =
                    __floats2half2_rn(c[mi][ni][0], c[mi][ni][1]);
            if (r0 + 8 < NN)
                *(__half2*)&g_ph[(size_t)(r0 + 8) * C1 + col] =
                    __floats2half2_rn(c[mi][ni][2], c[mi][ni][3]);
        }
    }
}

// ---------------- aggregation pass 1: g_hh = relu(agg(g_t1h) + b1) ---------
// 2-edge loop; packed {src,dinv} edges -> one sequential 8B load per edge.
__global__ void k_agg0(const float* __restrict__ bias) {
    int warp = threadIdx.x >> 5;
    int lane = threadIdx.x & 31;
    int i = blockIdx.x * 4 + warp;
    if (i >= NN) return;

    float di = g_dinv[i];
    float sw = di * di;

    const __half2* rowi = (const __half2*)&g_t1h[(size_t)i * C1 + lane * 4];
    float2 s01 = __half22float2(rowi[0]);
    float2 s23 = __half22float2(rowi[1]);
    float4 acc = make_float4(s01.x * sw, s01.y * sw, s23.x * sw, s23.y * sw);

    int e  = g_rowptr[i];
    int e1 = g_rowptr[i + 1];
    for (; e + 1 < e1; e += 2) {
        int2 e0 = g_edge[e], e1v = g_edge[e + 1];
        float w0 = __int_as_float(e0.y) * di;
        float w1 = __int_as_float(e1v.y) * di;
        const __half2* r0 = (const __half2*)&g_t1h[(size_t)e0.x * C1 + lane * 4];
        const __half2* r1 = (const __half2*)&g_t1h[(size_t)e1v.x * C1 + lane * 4];
        float2 a01 = __half22float2(r0[0]), a23 = __half22float2(r0[1]);
        float2 b01 = __half22float2(r1[0]), b23 = __half22float2(r1[1]);
        acc.x = fmaf(a01.x, w0, fmaf(b01.x, w1, acc.x));
        acc.y = fmaf(a01.y, w0, fmaf(b01.y, w1, acc.y));
        acc.z = fmaf(a23.x, w0, fmaf(b23.x, w1, acc.z));
        acc.w = fmaf(a23.y, w0, fmaf(b23.y, w1, acc.w));
    }
    if (e < e1) {
        int2 e0 = g_edge[e];
        float w0 = __int_as_float(e0.y) * di;
        const __half2* r0 = (const __half2*)&g_t1h[(size_t)e0.x * C1 + lane * 4];
        float2 a01 = __half22float2(r0[0]), a23 = __half22float2(r0[1]);
        acc.x = fmaf(a01.x, w0, acc.x);
        acc.y = fmaf(a01.y, w0, acc.y);
        acc.z = fmaf(a23.x, w0, acc.z);
        acc.w = fmaf(a23.y, w0, acc.w);
    }
    float4 b = *(const float4*)&bias[lane * 4];
    __half2 o0 = __floats2half2_rn(fmaxf(acc.x + b.x, 0.f), fmaxf(acc.y + b.y, 0.f));
    __half2 o1 = __floats2half2_rn(fmaxf(acc.z + b.z, 0.f), fmaxf(acc.w + b.w, 0.f));
    *(uint2*)&g_hh[(size_t)i * C1 + lane * 4] =
        make_uint2(*reinterpret_cast<uint32_t*>(&o0), *reinterpret_cast<uint32_t*>(&o1));
}

// ---------------- aggregation pass 2: out = agg(g_ph) + [bmu|bls] ----------
__global__ void k_agg_out(const float* __restrict__ bmu, const float* __restrict__ bls,
                          float* __restrict__ out) {
    int warp = threadIdx.x >> 5;
    int lane = threadIdx.x & 31;
    int i = blockIdx.x * 4 + warp;
    if (i >= NN) return;

    float di = g_dinv[i];
    float sw = di * di;

    const __half2* rowi = (const __half2*)&g_ph[(size_t)i * C1 + lane * 4];
    float2 s01 = __half22float2(rowi[0]);
    float2 s23 = __half22float2(rowi[1]);
    float4 acc = make_float4(s01.x * sw, s01.y * sw, s23.x * sw, s23.y * sw);

    int e  = g_rowptr[i];
    int e1 = g_rowptr[i + 1];
    for (; e + 1 < e1; e += 2) {
        int2 e0 = g_edge[e], e1v = g_edge[e + 1];
        float w0 = __int_as_float(e0.y) * di;
        float w1 = __int_as_float(e1v.y) * di;
        const __half2* r0 = (const __half2*)&g_ph[(size_t)e0.x * C1 + lane * 4];
        const __half2* r1 = (const __half2*)&g_ph[(size_t)e1v.x * C1 + lane * 4];
        float2 a01 = __half22float2(r0[0]), a23 = __half22float2(r0[1]);
        float2 b01 = __half22float2(r1[0]), b23 = __half22float2(r1[1]);
        acc.x = fmaf(a01.x, w0, fmaf(b01.x, w1, acc.x));
        acc.y = fmaf(a01.y, w0, fmaf(b01.y, w1, acc.y));
        acc.z = fmaf(a23.x, w0, fmaf(b23.x, w1, acc.z));
        acc.w = fmaf(a23.y, w0, fmaf(b23.y, w1, acc.w));
    }
    if (e < e1) {
        int2 e0 = g_edge[e];
        float w0 = __int_as_float(e0.y) * di;
        const __half2* r0 = (const __half2*)&g_ph[(size_t)e0.x * C1 + lane * 4];
        float2 a01 = __half22float2(r0[0]), a23 = __half22float2(r0[1]);
        acc.x = fmaf(a01.x, w0, acc.x);
        acc.y = fmaf(a01.y, w0, acc.y);
        acc.z = fmaf(a23.x, w0, acc.z);
        acc.w = fmaf(a23.y, w0, acc.w);
    }
    int col = lane * 4;
    if (col < HH) {
        float4 b = *(const float4*)&bmu[col];
        acc.x += b.x; acc.y += b.y; acc.z += b.z; acc.w += b.w;
        *(float4*)&out[(size_t)i * HH + col] = acc;
    } else {
        float4 b = *(const float4*)&bls[col - HH];
        acc.x += b.x; acc.y += b.y; acc.z += b.z; acc.w += b.w;
        *(float4*)&out[(size_t)(NN + i) * HH + (col - HH)] = acc;
    }
}

// ---------------- launch (single stream) ----------------
extern "C" void kernel_launch(void* const* d_in, const int* in_sizes, int n_in,
                              void* d_out, int out_size) {
    const float* x   = (const float*)d_in[0];
    const int*   ei  = (const int*)d_in[1];
    const float* W1  = (const float*)d_in[2];
    const float* b1  = (const float*)d_in[3];
    const float* Wmu = (const float*)d_in[4];
    const float* bmu = (const float*)d_in[5];
    const float* Wls = (const float*)d_in[6];
    const float* bls = (const float*)d_in[7];
    float* out = (float*)d_out;

    const int nb_n = (NN + 255) / 256;
    const int nb_e = (EE + 255) / 256;
    const int nb_s = (NN + 1023) / 1024;

    k_prep_w<<<nb_n, 256>>>(W1, Wmu, Wls);
    k_deg_count<<<nb_e, 256>>>(ei);
    k_gemm1<<<(NN + 127) / 128, 256>>>(x);
    k_scan_local<<<nb_s, 1024>>>();
    k_add_offsets<<<nb_n, 256>>>();
    k_scatter<<<nb_e, 256>>>(ei);

    k_agg0<<<(NN + 3) / 4, 128>>>(b1);
    k_gemm2b<<<(NN + 127) / 128, 256>>>();
    k_agg_out<<<(NN + 3) / 4, 128>>>(bmu, bls, out);
}

// round 16
// speedup vs baseline: 1.1120x; 1.1120x over previous
#include <cuda_runtime.h>
#include <cuda_fp16.h>
#include <cstdint>

#define NN  100000
#define EE  1600000
#define FIN 512
#define C1  128    // 2*H
#define HH  64

// ---------------- scratch (no allocations allowed) ----------------
__device__ __align__(16) __half g_t1h[(size_t)NN * C1];  // x @ W1 (fp16)
__device__ __align__(16) __half g_hh[(size_t)NN * C1];   // relu(agg(t1)+b1) (fp16)
__device__ __align__(16) __half g_ph[(size_t)NN * C1];   // h @ [Wmu|Wls] (fp16)
__device__ float g_dinv[NN];
__device__ int   g_deg[NN];
__device__ int   g_rowptr[NN + 1];
__device__ int   g_cursor[NN];
__device__ int   g_srcs[EE];
__device__ int   g_partial[128];
// weights as fp16, row-major [k][n=128]
__device__ __align__(16) __half g_w1h[FIN * C1];
__device__ __align__(16) __half g_wch[C1 * C1];

// ---------------- helpers ----------------
__device__ __forceinline__ uint32_t smem_u32(const void* p) {
    uint32_t a;
    asm("{ .reg .u64 t; cvta.to.shared.u64 t, %1; cvt.u32.u64 %0, t; }" : "=r"(a) : "l"(p));
    return a;
}
__device__ __forceinline__ uint32_t h2pack(float a, float b) {
    __half2 t = __floats2half2_rn(a, b);
    return *reinterpret_cast<uint32_t*>(&t);
}
__device__ __forceinline__ void ldsm_x4(uint32_t& r0, uint32_t& r1, uint32_t& r2, uint32_t& r3,
                                        uint32_t addr) {
    asm volatile("ldmatrix.sync.aligned.m8n8.x4.shared.b16 {%0,%1,%2,%3}, [%4];"
                 : "=r"(r0), "=r"(r1), "=r"(r2), "=r"(r3) : "r"(addr));
}
__device__ __forceinline__ void ldsm_x4_t(uint32_t& r0, uint32_t& r1, uint32_t& r2, uint32_t& r3,
                                          uint32_t addr) {
    asm volatile("ldmatrix.sync.aligned.m8n8.x4.trans.shared.b16 {%0,%1,%2,%3}, [%4];"
                 : "=r"(r0), "=r"(r1), "=r"(r2), "=r"(r3) : "r"(addr));
}
__device__ __forceinline__ void mma_f16(float* c, const uint32_t* a, const uint32_t* b) {
    asm volatile(
        "mma.sync.aligned.m16n8k16.row.col.f32.f16.f16.f32 "
        "{%0,%1,%2,%3}, {%4,%5,%6,%7}, {%8,%9}, {%0,%1,%2,%3};"
        : "+f"(c[0]), "+f"(c[1]), "+f"(c[2]), "+f"(c[3])
        : "r"(a[0]), "r"(a[1]), "r"(a[2]), "r"(a[3]), "r"(b[0]), "r"(b[1]));
}

// ---------------- weight preprocessing + deg init (fused) ------------------
__global__ void k_prep_w(const float* __restrict__ W1,
                         const float* __restrict__ Wmu, const float* __restrict__ Wls) {
    int idx = blockIdx.x * 256 + threadIdx.x;
    if (idx < FIN * C1) {
        g_w1h[idx] = __float2half(W1[idx]);          // W1 is [k][n] row-major already
    } else if (idx < FIN * C1 + C1 * C1) {
        int j = idx - FIN * C1;
        int k = j >> 7, n = j & 127;
        float w = (n < HH) ? Wmu[k * HH + n] : Wls[k * HH + (n - HH)];
        g_wch[j] = __float2half(w);
    }
    if (idx < NN) g_deg[idx] = 1;   // self-loop init
}

// ---------------- graph preprocessing ----------------
__global__ void k_deg_count(const int* __restrict__ ei) {
    int e = blockIdx.x * blockDim.x + threadIdx.x;
    if (e < EE) atomicAdd(&g_deg[ei[EE + e]], 1);
}

__global__ void k_scan_local() {
    __shared__ int sd[1024];
    int t = threadIdx.x;
    int i = blockIdx.x * 1024 + t;
    int v = (i < NN) ? (g_deg[i] - 1) : 0;
    sd[t] = v;
    __syncthreads();
#pragma unroll
    for (int off = 1; off < 1024; off <<= 1) {
        int x = (t >= off) ? sd[t - off] : 0;
        __syncthreads();
        sd[t] += x;
        __syncthreads();
    }
    if (i < NN) g_rowptr[i] = sd[t] - v;
    if (t == 1023) g_partial[blockIdx.x] = sd[1023];
}

__global__ void k_add_offsets() {
    __shared__ int base;
    int i = blockIdx.x * 256 + threadIdx.x;
    if (threadIdx.x == 0) {
        int nb = blockIdx.x >> 2;
        int s = 0;
        for (int b = 0; b < nb; b++) s += g_partial[b];
        base = s;
    }
    __syncthreads();
    if (i < NN) {
        int r = g_rowptr[i] + base;
        g_rowptr[i] = r;
        g_cursor[i] = r;
        g_dinv[i] = rsqrtf((float)g_deg[i]);
    }
    if (i == 0) g_rowptr[NN] = EE;
}

__global__ void k_scatter(const int* __restrict__ ei) {
    int e = blockIdx.x * blockDim.x + threadIdx.x;
    if (e < EE) {
        int s = ei[e];
        int d = ei[EE + e];
        int p = atomicAdd(&g_cursor[d], 1);
        g_srcs[p] = s;
    }
}

// ---------------- GEMM1 (mma.sync fp16 single-term, R3-proven layouts) -----
// t1[N,128](fp16) = x[N,512] @ W1[512,128]; CTA 128x128, 8 warps, warp 32x64.
#define A_STRIDE 80      // bytes per A smem row (32 fp16 + pad)
#define W_STRIDE 272     // bytes per W smem row (128 fp16 + pad)

__global__ void __launch_bounds__(256, 2)
k_gemm1(const float* __restrict__ x) {
    __shared__ __align__(16) unsigned char sA[128 * A_STRIDE];
    __shared__ __align__(16) unsigned char sW[32 * W_STRIDE];

    const int tid = threadIdx.x;
    const int wid = tid >> 5, lane = tid & 31;
    const int warp_m = wid & 3;
    const int warp_n = wid >> 2;
    const int block_row = blockIdx.x * 128;

    const uint32_t sA_u = smem_u32(sA), sW_u = smem_u32(sW);

    float c[2][8][4];
#pragma unroll
    for (int mi = 0; mi < 2; mi++)
#pragma unroll
        for (int ni = 0; ni < 8; ni++)
#pragma unroll
            for (int q = 0; q < 4; q++) c[mi][ni][q] = 0.f;

    const int lrow = lane & 15;
    const int lcol16 = (lane >> 4) * 16;

    for (int kc = 0; kc < FIN / 32; kc++) {
        // stage A (fp32 -> fp16): 128x32, 1024 float4, 4/thread
#pragma unroll
        for (int l = 0; l < 4; l++) {
            int f4 = tid + 256 * l;
            int r = f4 >> 3, c4 = f4 & 7;
            int grow = block_row + r;
            float4 v = make_float4(0.f, 0.f, 0.f, 0.f);
            if (grow < NN) v = *(const float4*)&x[(size_t)grow * FIN + kc * 32 + c4 * 4];
            *(uint2*)(sA + r * A_STRIDE + c4 * 8) =
                make_uint2(h2pack(v.x, v.y), h2pack(v.z, v.w));
        }
        // stage W: 32x128 fp16; 512 uint4, 2/thread
#pragma unroll
        for (int l = 0; l < 2; l++) {
            int u4 = tid + 256 * l;
            int r = u4 >> 4, c16 = u4 & 15;
            *(uint4*)(sW + r * W_STRIDE + c16 * 16) =
                *(const uint4*)&g_w1h[(size_t)(kc * 32 + r) * C1 + c16 * 8];
        }
        __syncthreads();

#pragma unroll
        for (int slab = 0; slab < 2; slab++) {      // two k16 slabs per chunk
            uint32_t a[2][4];
#pragma unroll
            for (int mi = 0; mi < 2; mi++) {
                uint32_t aoff = (uint32_t)(warp_m * 32 + mi * 16 + lrow) * A_STRIDE
                              + slab * 32 + lcol16;
                ldsm_x4(a[mi][0], a[mi][1], a[mi][2], a[mi][3], sA_u + aoff);
            }
#pragma unroll
            for (int h = 0; h < 2; h++) {
                uint32_t b[4][2];
#pragma unroll
                for (int q = 0; q < 2; q++) {
                    uint32_t boff = (uint32_t)(slab * 16 + lrow) * W_STRIDE
                                  + (warp_n * 64 + h * 32 + q * 16) * 2 + lcol16;
                    ldsm_x4_t(b[q * 2][0], b[q * 2][1], b[q * 2 + 1][0], b[q * 2 + 1][1],
                              sW_u + boff);
                }
#pragma unroll
                for (int mi = 0; mi < 2; mi++)
#pragma unroll
                    for (int nn = 0; nn < 4; nn++)
                        mma_f16(c[mi][h * 4 + nn], a[mi], b[nn]);
            }
        }
        __syncthreads();
    }

    const int qrow = lane >> 2;
    const int qcol = (lane & 3) * 2;
#pragma unroll
    for (int mi = 0; mi < 2; mi++) {
        int r0 = block_row + warp_m * 32 + mi * 16 + qrow;
#pragma unroll
        for (int ni = 0; ni < 8; ni++) {
            int col = warp_n * 64 + ni * 8 + qcol;
            if (r0 < NN)
                *(__half2*)&g_t1h[(size_t)r0 * C1 + col] =
                    __floats2half2_rn(c[mi][ni][0], c[mi][ni][1]);
            if (r0 + 8 < NN)
                *(__half2*)&g_t1h[(size_t)(r0 + 8) * C1 + col] =
                    __floats2half2_rn(c[mi][ni][2], c[mi][ni][3]);
        }
    }
}

// ---------------- GEMM2b: p(fp16) = h(fp16) @ [Wmu|Wls](fp16) --------------
// A staging is a straight copy (h already fp16). Zero params (register cliff).
__global__ void __launch_bounds__(256, 2)
k_gemm2b() {
    __shared__ __align__(16) unsigned char sA[128 * A_STRIDE];
    __shared__ __align__(16) unsigned char sW[32 * W_STRIDE];

    const int tid = threadIdx.x;
    const int wid = tid >> 5, lane = tid & 31;
    const int warp_m = wid & 3;
    const int warp_n = wid >> 2;
    const int block_row = blockIdx.x * 128;

    const uint32_t sA_u = smem_u32(sA), sW_u = smem_u32(sW);

    float c[2][8][4];
#pragma unroll
    for (int mi = 0; mi < 2; mi++)
#pragma unroll
        for (int ni = 0; ni < 8; ni++)
#pragma unroll
            for (int q = 0; q < 4; q++) c[mi][ni][q] = 0.f;

    const int lrow = lane & 15;
    const int lcol16 = (lane >> 4) * 16;

#pragma unroll 1
    for (int kc = 0; kc < C1 / 32; kc++) {
        // stage A: straight fp16 copy, 128x32 halves = 512 uint4, 2/thread
#pragma unroll
        for (int l = 0; l < 2; l++) {
            int u4 = tid + 256 * l;
            int r = u4 >> 2, c4 = u4 & 3;
            int grow = block_row + r;
            uint4 v = make_uint4(0u, 0u, 0u, 0u);
            if (grow < NN) v = *(const uint4*)&g_hh[(size_t)grow * C1 + kc * 32 + c4 * 8];
            *(uint4*)(sA + r * A_STRIDE + c4 * 16) = v;
        }
#pragma unroll
        for (int l = 0; l < 2; l++) {
            int u4 = tid + 256 * l;
            int r = u4 >> 4, c16 = u4 & 15;
            *(uint4*)(sW + r * W_STRIDE + c16 * 16) =
                *(const uint4*)&g_wch[(size_t)(kc * 32 + r) * C1 + c16 * 8];
        }
        __syncthreads();

#pragma unroll
        for (int slab = 0; slab < 2; slab++) {
            uint32_t a[2][4];
#pragma unroll
            for (int mi = 0; mi < 2; mi++) {
                uint32_t aoff = (uint32_t)(warp_m * 32 + mi * 16 + lrow) * A_STRIDE
                              + slab * 32 + lcol16;
                ldsm_x4(a[mi][0], a[mi][1], a[mi][2], a[mi][3], sA_u + aoff);
            }
#pragma unroll
            for (int h = 0; h < 2; h++) {
                uint32_t b[4][2];
#pragma unroll
                for (int q = 0; q < 2; q++) {
                    uint32_t boff = (uint32_t)(slab * 16 + lrow) * W_STRIDE
                                  + (warp_n * 64 + h * 32 + q * 16) * 2 + lcol16;
                    ldsm_x4_t(b[q * 2][0], b[q * 2][1], b[q * 2 + 1][0], b[q * 2 + 1][1],
                              sW_u + boff);
                }
#pragma unroll
                for (int mi = 0; mi < 2; mi++)
#pragma unroll
                    for (int nn = 0; nn < 4; nn++)
                        mma_f16(c[mi][h * 4 + nn], a[mi], b[nn]);
            }
        }
        __syncthreads();
    }

    const int qrow = lane >> 2;
    const int qcol = (lane & 3) * 2;
#pragma unroll
    for (int mi = 0; mi < 2; mi++) {
        int r0 = block_row + warp_m * 32 + mi * 16 + qrow;
#pragma unroll
        for (int ni = 0; ni < 8; ni++) {
            int col = warp_n * 64 + ni * 8 + qcol;
            if (r0 < NN)
                *(__half2*)&g_ph[(size_t)r0 * C1 + col] =
                    __floats2half2_rn(c[mi][ni][0], c[mi][ni][1]);
            if (r0 + 8 < NN)
                *(__half2*)&g_ph[(size_t)(r0 + 8) * C1 + col] =
                    __floats2half2_rn(c[mi][ni][2], c[mi][ni][3]);
        }
    }
}

// ---------------- aggregation pass 1: g_hh = relu(agg(g_t1h) + b1) ---------
// R14 form (best measured): 2-edge loop, fp16 gathers, fp32 accumulation.
__global__ void k_agg0(const float* __restrict__ bias) {
    int warp = threadIdx.x >> 5;
    int lane = threadIdx.x & 31;
    int i = blockIdx.x * 4 + warp;
    if (i >= NN) return;

    float di = g_dinv[i];
    float sw = di * di;

    const __half2* rowi = (const __half2*)&g_t1h[(size_t)i * C1 + lane * 4];
    float2 s01 = __half22float2(rowi[0]);
    float2 s23 = __half22float2(rowi[1]);
    float4 acc = make_float4(s01.x * sw, s01.y * sw, s23.x * sw, s23.y * sw);

    int e  = g_rowptr[i];
    int e1 = g_rowptr[i + 1];
    for (; e + 1 < e1; e += 2) {
        int s0 = g_srcs[e], s1 = g_srcs[e + 1];
        float w0 = g_dinv[s0] * di;
        float w1 = g_dinv[s1] * di;
        const __half2* r0 = (const __half2*)&g_t1h[(size_t)s0 * C1 + lane * 4];
        const __half2* r1 = (const __half2*)&g_t1h[(size_t)s1 * C1 + lane * 4];
        float2 a01 = __half22float2(r0[0]), a23 = __half22float2(r0[1]);
        float2 b01 = __half22float2(r1[0]), b23 = __half22float2(r1[1]);
        acc.x = fmaf(a01.x, w0, fmaf(b01.x, w1, acc.x));
        acc.y = fmaf(a01.y, w0, fmaf(b01.y, w1, acc.y));
        acc.z = fmaf(a23.x, w0, fmaf(b23.x, w1, acc.z));
        acc.w = fmaf(a23.y, w0, fmaf(b23.y, w1, acc.w));
    }
    if (e < e1) {
        int s0 = g_srcs[e];
        float w0 = g_dinv[s0] * di;
        const __half2* r0 = (const __half2*)&g_t1h[(size_t)s0 * C1 + lane * 4];
        float2 a01 = __half22float2(r0[0]), a23 = __half22float2(r0[1]);
        acc.x = fmaf(a01.x, w0, acc.x);
        acc.y = fmaf(a01.y, w0, acc.y);
        acc.z = fmaf(a23.x, w0, acc.z);
        acc.w = fmaf(a23.y, w0, acc.w);
    }
    float4 b = *(const float4*)&bias[lane * 4];
    __half2 o0 = __floats2half2_rn(fmaxf(acc.x + b.x, 0.f), fmaxf(acc.y + b.y, 0.f));
    __half2 o1 = __floats2half2_rn(fmaxf(acc.z + b.z, 0.f), fmaxf(acc.w + b.w, 0.f));
    *(uint2*)&g_hh[(size_t)i * C1 + lane * 4] =
        make_uint2(*reinterpret_cast<uint32_t*>(&o0), *reinterpret_cast<uint32_t*>(&o1));
}

// ---------------- aggregation pass 2: out = agg(g_ph) + [bmu|bls] ----------
__global__ void k_agg_out(const float* __restrict__ bmu, const float* __restrict__ bls,
                          float* __restrict__ out) {
    int warp = threadIdx.x >> 5;
    int lane = threadIdx.x & 31;
    int i = blockIdx.x * 4 + warp;
    if (i >= NN) return;

    float di = g_dinv[i];
    float sw = di * di;

    const __half2* rowi = (const __half2*)&g_ph[(size_t)i * C1 + lane * 4];
    float2 s01 = __half22float2(rowi[0]);
    float2 s23 = __half22float2(rowi[1]);
    float4 acc = make_float4(s01.x * sw, s01.y * sw, s23.x * sw, s23.y * sw);

    int e  = g_rowptr[i];
    int e1 = g_rowptr[i + 1];
    for (; e + 1 < e1; e += 2) {
        int s0 = g_srcs[e], s1 = g_srcs[e + 1];
        float w0 = g_dinv[s0] * di;
        float w1 = g_dinv[s1] * di;
        const __half2* r0 = (const __half2*)&g_ph[(size_t)s0 * C1 + lane * 4];
        const __half2* r1 = (const __half2*)&g_ph[(size_t)s1 * C1 + lane * 4];
        float2 a01 = __half22float2(r0[0]), a23 = __half22float2(r0[1]);
        float2 b01 = __half22float2(r1[0]), b23 = __half22float2(r1[1]);
        acc.x = fmaf(a01.x, w0, fmaf(b01.x, w1, acc.x));
        acc.y = fmaf(a01.y, w0, fmaf(b01.y, w1, acc.y));
        acc.z = fmaf(a23.x, w0, fmaf(b23.x, w1, acc.z));
        acc.w = fmaf(a23.y, w0, fmaf(b23.y, w1, acc.w));
    }
    if (e < e1) {
        int s0 = g_srcs[e];
        float w0 = g_dinv[s0] * di;
        const __half2* r0 = (const __half2*)&g_ph[(size_t)s0 * C1 + lane * 4];
        float2 a01 = __half22float2(r0[0]), a23 = __half22float2(r0[1]);
        acc.x = fmaf(a01.x, w0, acc.x);
        acc.y = fmaf(a01.y, w0, acc.y);
        acc.z = fmaf(a23.x, w0, acc.z);
        acc.w = fmaf(a23.y, w0, acc.w);
    }
    int col = lane * 4;
    if (col < HH) {
        float4 b = *(const float4*)&bmu[col];
        acc.x += b.x; acc.y += b.y; acc.z += b.z; acc.w += b.w;
        *(float4*)&out[(size_t)i * HH + col] = acc;
    } else {
        float4 b = *(const float4*)&bls[col - HH];
        acc.x += b.x; acc.y += b.y; acc.z += b.z; acc.w += b.w;
        *(float4*)&out[(size_t)(NN + i) * HH + (col - HH)] = acc;
    }
}

// ---------------- launch (single stream) ----------------
extern "C" void kernel_launch(void* const* d_in, const int* in_sizes, int n_in,
                              void* d_out, int out_size) {
    const float* x   = (const float*)d_in[0];
    const int*   ei  = (const int*)d_in[1];
    const float* W1  = (const float*)d_in[2];
    const float* b1  = (const float*)d_in[3];
    const float* Wmu = (const float*)d_in[4];
    const float* bmu = (const float*)d_in[5];
    const float* Wls = (const float*)d_in[6];
    const float* bls = (const float*)d_in[7];
    float* out = (float*)d_out;

    const int nb_n = (NN + 255) / 256;
    const int nb_e = (EE + 255) / 256;
    const int nb_s = (NN + 1023) / 1024;

    k_prep_w<<<nb_n, 256>>>(W1, Wmu, Wls);
    k_deg_count<<<nb_e, 256>>>(ei);
    k_gemm1<<<(NN + 127) / 128, 256>>>(x);
    k_scan_local<<<nb_s, 1024>>>();
    k_add_offsets<<<nb_n, 256>>>();
    k_scatter<<<nb_e, 256>>>(ei);

    k_agg0<<<(NN + 3) / 4, 128>>>(b1);
    k_gemm2b<<<(NN + 127) / 128, 256>>>();
    k_agg_out<<<(NN + 3) / 4, 128>>>(bmu, bls, out);
}